// round 10
// baseline (speedup 1.0000x reference)
#include <cuda_runtime.h>
#include <cuda_bf16.h>
#include <math_constants.h>

#define N_NODES 100000
#define N_EDGES 1600000
#define IN_CH   128
#define OUT_CH  64
#define NEG_SLOPE 0.2f
#define EPS_F 1e-10f

#define SCAN_BS 1024
#define NUM_SCAN_BLOCKS ((N_NODES + SCAN_BS - 1) / SCAN_BS)   // 98

// ---------------- scratch (no allocations allowed) ----------------
__device__ float g_h[(size_t)N_NODES * OUT_CH];   // 25.6 MB
__device__ float g_el[N_NODES];
__device__ float g_er[N_NODES];
__device__ int   g_deg[N_NODES];
__device__ int   g_fill[N_NODES];                 // preloaded with rowptr starts
__device__ int   g_rowptr[N_NODES + 1];
__device__ int   g_bsum[NUM_SCAN_BLOCKS];
__device__ int2  g_edge_sorted[N_EDGES];          // (src, w-bits) 12.8 MB

__device__ __forceinline__ float leaky(float v) {
    return v > 0.0f ? v : NEG_SLOPE * v;
}

// ---------------- K0: zero deg ----------------
__global__ void init_kernel() {
    int i = blockIdx.x * blockDim.x + threadIdx.x;
    if (i < N_NODES) g_deg[i] = 0;
}

// ================= gemm: split-bf16 tensor-core GEMM + fused elr =================
#define GEMM_ROWS 128
#define XS_STRIDE 136                       // bf16 elems per row (272B, conflict-free)
#define XS_ELEMS  (GEMM_ROWS * XS_STRIDE)   // 17408
#define WS_ELEMS  (OUT_CH * XS_STRIDE)      // 8704
#define GEMM_SMEM_BYTES ((2 * XS_ELEMS + 2 * WS_ELEMS) * 2)   // 104448

__device__ __forceinline__ void store_split4(__nv_bfloat16* hi, __nv_bfloat16* lo,
                                             int idx, float4 v) {
    float f[4] = {v.x, v.y, v.z, v.w};
    unsigned hb[4], lb[4];
#pragma unroll
    for (int j = 0; j < 4; j++) {
        __nv_bfloat16 h = __float2bfloat16_rn(f[j]);
        float hf = __bfloat162float(h);
        __nv_bfloat16 l = __float2bfloat16_rn(f[j] - hf);
        hb[j] = (unsigned)__bfloat16_as_ushort(h);
        lb[j] = (unsigned)__bfloat16_as_ushort(l);
    }
    unsigned* ph = reinterpret_cast<unsigned*>(hi + idx);
    unsigned* pl = reinterpret_cast<unsigned*>(lo + idx);
    ph[0] = hb[0] | (hb[1] << 16);
    ph[1] = hb[2] | (hb[3] << 16);
    pl[0] = lb[0] | (lb[1] << 16);
    pl[1] = lb[2] | (lb[3] << 16);
}

__device__ __forceinline__ void mma16816(float d[4], const unsigned a[4], const unsigned b[2]) {
    asm volatile(
        "mma.sync.aligned.m16n8k16.row.col.f32.bf16.bf16.f32 "
        "{%0,%1,%2,%3}, {%4,%5,%6,%7}, {%8,%9}, {%0,%1,%2,%3};\n"
        : "+f"(d[0]), "+f"(d[1]), "+f"(d[2]), "+f"(d[3])
        : "r"(a[0]), "r"(a[1]), "r"(a[2]), "r"(a[3]), "r"(b[0]), "r"(b[1]));
}

__device__ __forceinline__ void gemm_pass(const __nv_bfloat16* xa, const __nv_bfloat16* wb,
                                          int wm, int wn, int g, int tig,
                                          float d[2][4][4]) {
#pragma unroll
    for (int ks = 0; ks < 8; ks++) {
        int k0 = ks * 16;
        unsigned a[2][4];
        unsigned b[4][2];
#pragma unroll
        for (int mi = 0; mi < 2; mi++) {
            int rb = wm * 32 + mi * 16;
            a[mi][0] = *reinterpret_cast<const unsigned*>(xa + (rb + g)     * XS_STRIDE + k0 + tig * 2);
            a[mi][1] = *reinterpret_cast<const unsigned*>(xa + (rb + g + 8) * XS_STRIDE + k0 + tig * 2);
            a[mi][2] = *reinterpret_cast<const unsigned*>(xa + (rb + g)     * XS_STRIDE + k0 + tig * 2 + 8);
            a[mi][3] = *reinterpret_cast<const unsigned*>(xa + (rb + g + 8) * XS_STRIDE + k0 + tig * 2 + 8);
        }
#pragma unroll
        for (int ni = 0; ni < 4; ni++) {
            int oc = wn * 32 + ni * 8 + g;
            b[ni][0] = *reinterpret_cast<const unsigned*>(wb + oc * XS_STRIDE + k0 + tig * 2);
            b[ni][1] = *reinterpret_cast<const unsigned*>(wb + oc * XS_STRIDE + k0 + tig * 2 + 8);
        }
#pragma unroll
        for (int mi = 0; mi < 2; mi++)
#pragma unroll
            for (int ni = 0; ni < 4; ni++)
                mma16816(d[mi][ni], a[mi], b[ni]);
    }
}

__global__ __launch_bounds__(256) void gemm_kernel(const float* __restrict__ x,
                                                   const float* __restrict__ W,
                                                   const float* __restrict__ a_l,
                                                   const float* __restrict__ a_r) {
    extern __shared__ __align__(16) char dynsmem[];
    __nv_bfloat16* xs_hi = reinterpret_cast<__nv_bfloat16*>(dynsmem);
    __nv_bfloat16* xs_lo = xs_hi + XS_ELEMS;
    __nv_bfloat16* ws_hi = xs_lo + XS_ELEMS;
    __nv_bfloat16* ws_lo = ws_hi + WS_ELEMS;
    __shared__ float s_el[GEMM_ROWS];
    __shared__ float s_er[GEMM_ROWS];

    int tid = threadIdx.x;
    int row0 = blockIdx.x * GEMM_ROWS;

    if (tid < GEMM_ROWS) { s_el[tid] = 0.0f; s_er[tid] = 0.0f; }

    for (int i = tid; i < GEMM_ROWS * (IN_CH / 4); i += 256) {
        int r  = i >> 5;
        int c4 = (i & 31) << 2;
        int row = row0 + r;
        float4 v = make_float4(0.f, 0.f, 0.f, 0.f);
        if (row < N_NODES) v = *reinterpret_cast<const float4*>(x + (size_t)row * IN_CH + c4);
        store_split4(xs_hi, xs_lo, r * XS_STRIDE + c4, v);
    }
    for (int i = tid; i < OUT_CH * (IN_CH / 4); i += 256) {
        int r  = i >> 5;
        int c4 = (i & 31) << 2;
        float4 v = *reinterpret_cast<const float4*>(W + (size_t)r * IN_CH + c4);
        store_split4(ws_hi, ws_lo, r * XS_STRIDE + c4, v);
    }
    __syncthreads();

    int lane = tid & 31, wid = tid >> 5;
    int wm = wid & 3, wn = wid >> 2;
    int g = lane >> 2, tig = lane & 3;

    float d[2][4][4];
#pragma unroll
    for (int mi = 0; mi < 2; mi++)
#pragma unroll
        for (int ni = 0; ni < 4; ni++)
#pragma unroll
            for (int q = 0; q < 4; q++) d[mi][ni][q] = 0.0f;

    gemm_pass(xs_hi, ws_hi, wm, wn, g, tig, d);
    gemm_pass(xs_lo, ws_hi, wm, wn, g, tig, d);
    gemm_pass(xs_hi, ws_lo, wm, wn, g, tig, d);

    float alv[4][2], arv[4][2];
#pragma unroll
    for (int ni = 0; ni < 4; ni++) {
        int c = wn * 32 + ni * 8 + tig * 2;
        alv[ni][0] = a_l[c];     alv[ni][1] = a_l[c + 1];
        arv[ni][0] = a_r[c];     arv[ni][1] = a_r[c + 1];
    }

#pragma unroll
    for (int mi = 0; mi < 2; mi++) {
        int r1 = wm * 32 + mi * 16 + g;
        int r2 = r1 + 8;
        int grow1 = row0 + r1, grow2 = row0 + r2;
        float sl1 = 0.f, sr1 = 0.f, sl2 = 0.f, sr2 = 0.f;
#pragma unroll
        for (int ni = 0; ni < 4; ni++) {
            int c = wn * 32 + ni * 8 + tig * 2;
            float d0 = d[mi][ni][0], d1 = d[mi][ni][1];
            float d2 = d[mi][ni][2], d3 = d[mi][ni][3];
            sl1 = fmaf(d0, alv[ni][0], fmaf(d1, alv[ni][1], sl1));
            sr1 = fmaf(d0, arv[ni][0], fmaf(d1, arv[ni][1], sr1));
            sl2 = fmaf(d2, alv[ni][0], fmaf(d3, alv[ni][1], sl2));
            sr2 = fmaf(d2, arv[ni][0], fmaf(d3, arv[ni][1], sr2));
            if (grow1 < N_NODES)
                *reinterpret_cast<float2*>(g_h + (size_t)grow1 * OUT_CH + c) = make_float2(d0, d1);
            if (grow2 < N_NODES)
                *reinterpret_cast<float2*>(g_h + (size_t)grow2 * OUT_CH + c) = make_float2(d2, d3);
        }
#pragma unroll
        for (int m = 1; m < 4; m <<= 1) {
            sl1 += __shfl_xor_sync(0xFFFFFFFFu, sl1, m);
            sr1 += __shfl_xor_sync(0xFFFFFFFFu, sr1, m);
            sl2 += __shfl_xor_sync(0xFFFFFFFFu, sl2, m);
            sr2 += __shfl_xor_sync(0xFFFFFFFFu, sr2, m);
        }
        if (tig == 0) {
            atomicAdd(&s_el[r1], sl1); atomicAdd(&s_er[r1], sr1);
            atomicAdd(&s_el[r2], sl2); atomicAdd(&s_er[r2], sr2);
        }
    }
    __syncthreads();
    if (tid < GEMM_ROWS) {
        int row = row0 + tid;
        if (row < N_NODES) { g_el[row] = s_el[tid]; g_er[row] = s_er[tid]; }
    }
}

// ---------------- hist: histogram of dst (4 edges/thread, int4) ----------------
__global__ void hist_kernel(const int* __restrict__ ei) {
    int t = blockIdx.x * blockDim.x + threadIdx.x;
    int e4 = t * 4;
    if (e4 >= N_EDGES) return;
    int4 d = *reinterpret_cast<const int4*>(ei + N_EDGES + e4);
    atomicAdd(&g_deg[d.x], 1);
    atomicAdd(&g_deg[d.y], 1);
    atomicAdd(&g_deg[d.z], 1);
    atomicAdd(&g_deg[d.w], 1);
}

// ---------------- scan a: per-block inclusive scan of deg ----------------
__global__ void scan_block_kernel() {
    __shared__ int warp_sums[32];
    int i = blockIdx.x * SCAN_BS + threadIdx.x;
    int lane = threadIdx.x & 31, wid = threadIdx.x >> 5;
    int v = (i < N_NODES) ? g_deg[i] : 0;
    int s = v;
#pragma unroll
    for (int o = 1; o < 32; o <<= 1) {
        int t = __shfl_up_sync(0xFFFFFFFFu, s, o);
        if (lane >= o) s += t;
    }
    if (lane == 31) warp_sums[wid] = s;
    __syncthreads();
    if (wid == 0) {
        int ws = warp_sums[lane];
#pragma unroll
        for (int o = 1; o < 32; o <<= 1) {
            int t = __shfl_up_sync(0xFFFFFFFFu, ws, o);
            if (lane >= o) ws += t;
        }
        warp_sums[lane] = ws;
    }
    __syncthreads();
    int incl = s + (wid > 0 ? warp_sums[wid - 1] : 0);
    if (i < N_NODES) g_rowptr[i + 1] = incl;
    if (threadIdx.x == SCAN_BS - 1) g_bsum[blockIdx.x] = incl;
}

// ---------------- scan b: exclusive scan of block sums (1 block) ----------------
__global__ void scan_bsum_kernel() {
    __shared__ int sh[NUM_SCAN_BLOCKS];
    int t = threadIdx.x;
    if (t < NUM_SCAN_BLOCKS) sh[t] = g_bsum[t];
    __syncthreads();
    if (t == 0) {
        int run = 0;
        for (int b = 0; b < NUM_SCAN_BLOCKS; b++) {
            int v = sh[b];
            sh[b] = run;
            run += v;
        }
    }
    __syncthreads();
    if (t < NUM_SCAN_BLOCKS) g_bsum[t] = sh[t];
}

// ---------------- scan c: finalize rowptr AND preload g_fill ----------------
__global__ void scan_add_kernel() {
    int i = blockIdx.x * blockDim.x + threadIdx.x;
    if (i < N_NODES) {
        int v = g_rowptr[i + 1] + g_bsum[i >> 10];
        g_rowptr[i + 1] = v;
        if (i + 1 < N_NODES) g_fill[i + 1] = v;
    }
    if (i == 0) { g_rowptr[0] = 0; g_fill[0] = 0; }
}

// ---------------- scatter: compute softmax weight, store (src, w) CSR-ordered ----------------
__global__ void scatter_kernel(const int* __restrict__ ei) {
    int t = blockIdx.x * blockDim.x + threadIdx.x;
    int e4 = t * 4;
    if (e4 >= N_EDGES) return;
    int4 s = *reinterpret_cast<const int4*>(ei + e4);
    int4 d = *reinterpret_cast<const int4*>(ei + N_EDGES + e4);
#pragma unroll
    for (int j = 0; j < 4; j++) {
        int src = (j == 0) ? s.x : (j == 1) ? s.y : (j == 2) ? s.z : s.w;
        int dst = (j == 0) ? d.x : (j == 1) ? d.y : (j == 2) ? d.z : d.w;
        float w = __expf(leaky(__ldg(&g_el[dst]) + __ldg(&g_er[src])));
        int pos = atomicAdd(&g_fill[dst], 1);
        g_edge_sorted[pos] = make_int2(src, __float_as_int(w));
    }
}

// ---------------- msg: pure gather+fma, 2 warps per node, unroll x4 ----------------
// NOTE: max-shift dropped; differs from reference by eps*(e^max-1)/sum ~ 3e-8.
__global__ void msg_kernel(float* __restrict__ out, const float* __restrict__ bias) {
    int gtid = blockIdx.x * blockDim.x + threadIdx.x;
    int w = gtid >> 5;
    int node = w >> 1;
    if (node >= N_NODES) return;
    int half = w & 1;
    int lane = gtid & 31;
    int chan = half * 32 + lane;
    int p   = g_rowptr[node];
    int end = g_rowptr[node + 1];
    float acc = 0.0f, wsum = 0.0f;
    for (; p + 4 <= end; p += 4) {
        int2 e0 = __ldg(&g_edge_sorted[p]);
        int2 e1 = __ldg(&g_edge_sorted[p + 1]);
        int2 e2 = __ldg(&g_edge_sorted[p + 2]);
        int2 e3 = __ldg(&g_edge_sorted[p + 3]);
        float h0 = __ldg(&g_h[(size_t)e0.x * OUT_CH + chan]);
        float h1 = __ldg(&g_h[(size_t)e1.x * OUT_CH + chan]);
        float h2 = __ldg(&g_h[(size_t)e2.x * OUT_CH + chan]);
        float h3 = __ldg(&g_h[(size_t)e3.x * OUT_CH + chan]);
        float w0 = __int_as_float(e0.y);
        float w1 = __int_as_float(e1.y);
        float w2 = __int_as_float(e2.y);
        float w3 = __int_as_float(e3.y);
        wsum += (w0 + w1) + (w2 + w3);
        acc = fmaf(w0, h0, acc);
        acc = fmaf(w1, h1, acc);
        acc = fmaf(w2, h2, acc);
        acc = fmaf(w3, h3, acc);
    }
    for (; p < end; p++) {
        int2 e0 = __ldg(&g_edge_sorted[p]);
        float w0 = __int_as_float(e0.y);
        wsum += w0;
        acc = fmaf(w0, __ldg(&g_h[(size_t)e0.x * OUT_CH + chan]), acc);
    }
    out[(size_t)node * OUT_CH + chan] = acc / (wsum + EPS_F) + bias[chan];
}

// ---------------- launch ----------------
extern "C" void kernel_launch(void* const* d_in, const int* in_sizes, int n_in,
                              void* d_out, int out_size) {
    const float* x    = (const float*)d_in[0];
    const int*   ei   = (const int*)d_in[1];     // int32 (JAX x64 disabled)
    const float* W    = (const float*)d_in[2];
    const float* a_l  = (const float*)d_in[3];
    const float* a_r  = (const float*)d_in[4];
    const float* bias = (const float*)d_in[5];
    float* out = (float*)d_out;

    (void)in_sizes; (void)n_in; (void)out_size;

    cudaFuncSetAttribute(gemm_kernel, cudaFuncAttributeMaxDynamicSharedMemorySize,
                         GEMM_SMEM_BYTES);

    // Launch order chosen so gemm is launch index 3 (ncu profiles index 3).
    init_kernel<<<(N_NODES + 255) / 256, 256>>>();                    // 0
    hist_kernel<<<(N_EDGES / 4 + 255) / 256, 256>>>(ei);              // 1
    scan_block_kernel<<<NUM_SCAN_BLOCKS, SCAN_BS>>>();                // 2
    gemm_kernel<<<(N_NODES + GEMM_ROWS - 1) / GEMM_ROWS, 256,
                  GEMM_SMEM_BYTES>>>(x, W, a_l, a_r);                 // 3  <-- profiled
    scan_bsum_kernel<<<1, 128>>>();                                   // 4
    scan_add_kernel<<<(N_NODES + 255) / 256, 256>>>();                // 5
    scatter_kernel<<<(N_EDGES / 4 + 255) / 256, 256>>>(ei);           // 6
    {
        long long threads = (long long)N_NODES * 64;   // 2 warps per node
        int blocks = (int)((threads + 255) / 256);
        msg_kernel<<<blocks, 256>>>(out, bias);                       // 7
    }
}

// round 11
// speedup vs baseline: 1.6179x; 1.6179x over previous
#include <cuda_runtime.h>
#include <cuda_bf16.h>
#include <math_constants.h>

#define N_NODES 100000
#define N_EDGES 1600000
#define IN_CH   128
#define OUT_CH  64
#define NEG_SLOPE 0.2f
#define EPS_F 1e-10f

#define SCAN_BS 1024
#define NUM_SCAN_BLOCKS ((N_NODES + SCAN_BS - 1) / SCAN_BS)   // 98

// ---------------- scratch (no allocations allowed) ----------------
__device__ float g_h[(size_t)N_NODES * OUT_CH];   // 25.6 MB
__device__ float g_el[N_NODES];
__device__ float g_er[N_NODES];
__device__ int   g_deg[N_NODES];
__device__ int   g_fill[N_NODES];                 // preloaded with rowptr starts
__device__ int   g_rowptr[N_NODES + 1];
__device__ int   g_bsum[NUM_SCAN_BLOCKS];
__device__ int2  g_edge_sorted[N_EDGES];          // (src, er-bits) 12.8 MB

__device__ __forceinline__ float leaky(float v) {
    return v > 0.0f ? v : NEG_SLOPE * v;
}

// ---------------- K0: zero deg ----------------
__global__ void init_kernel() {
    int i = blockIdx.x * blockDim.x + threadIdx.x;
    if (i < N_NODES) g_deg[i] = 0;
}

// ================= gemm: split-bf16 tensor-core GEMM + fused elr =================
// 64 rows x 64 cols per block, K=128 resident. 256 threads = 8 warps.
// smem ~68KB + <=128 regs -> 2 blocks/SM (16 warps) vs previous 1 block.
#define GEMM_ROWS 64
#define XS_STRIDE 136                       // bf16 elems per row (272B, conflict-free)
#define XS_ELEMS  (GEMM_ROWS * XS_STRIDE)   // 8704
#define WS_ELEMS  (OUT_CH * XS_STRIDE)      // 8704
#define GEMM_SMEM_BYTES ((2 * XS_ELEMS + 2 * WS_ELEMS) * 2)   // 69632

__device__ __forceinline__ void store_split4(__nv_bfloat16* hi, __nv_bfloat16* lo,
                                             int idx, float4 v) {
    float f[4] = {v.x, v.y, v.z, v.w};
    unsigned hb[4], lb[4];
#pragma unroll
    for (int j = 0; j < 4; j++) {
        __nv_bfloat16 h = __float2bfloat16_rn(f[j]);
        float hf = __bfloat162float(h);
        __nv_bfloat16 l = __float2bfloat16_rn(f[j] - hf);
        hb[j] = (unsigned)__bfloat16_as_ushort(h);
        lb[j] = (unsigned)__bfloat16_as_ushort(l);
    }
    unsigned* ph = reinterpret_cast<unsigned*>(hi + idx);
    unsigned* pl = reinterpret_cast<unsigned*>(lo + idx);
    ph[0] = hb[0] | (hb[1] << 16);
    ph[1] = hb[2] | (hb[3] << 16);
    pl[0] = lb[0] | (lb[1] << 16);
    pl[1] = lb[2] | (lb[3] << 16);
}

__device__ __forceinline__ void mma16816(float d[4], const unsigned a[4], const unsigned b[2]) {
    asm volatile(
        "mma.sync.aligned.m16n8k16.row.col.f32.bf16.bf16.f32 "
        "{%0,%1,%2,%3}, {%4,%5,%6,%7}, {%8,%9}, {%0,%1,%2,%3};\n"
        : "+f"(d[0]), "+f"(d[1]), "+f"(d[2]), "+f"(d[3])
        : "r"(a[0]), "r"(a[1]), "r"(a[2]), "r"(a[3]), "r"(b[0]), "r"(b[1]));
}

// per-warp tile: rows wm*32 (2x m16), cols wn*16 (2x n8)
__device__ __forceinline__ void gemm_pass(const __nv_bfloat16* xa, const __nv_bfloat16* wb,
                                          int wm, int wn, int g, int tig,
                                          float d[2][2][4]) {
#pragma unroll
    for (int ks = 0; ks < 8; ks++) {
        int k0 = ks * 16;
        unsigned a[2][4];
        unsigned b[2][2];
#pragma unroll
        for (int mi = 0; mi < 2; mi++) {
            int rb = wm * 32 + mi * 16;
            a[mi][0] = *reinterpret_cast<const unsigned*>(xa + (rb + g)     * XS_STRIDE + k0 + tig * 2);
            a[mi][1] = *reinterpret_cast<const unsigned*>(xa + (rb + g + 8) * XS_STRIDE + k0 + tig * 2);
            a[mi][2] = *reinterpret_cast<const unsigned*>(xa + (rb + g)     * XS_STRIDE + k0 + tig * 2 + 8);
            a[mi][3] = *reinterpret_cast<const unsigned*>(xa + (rb + g + 8) * XS_STRIDE + k0 + tig * 2 + 8);
        }
#pragma unroll
        for (int ni = 0; ni < 2; ni++) {
            int oc = wn * 16 + ni * 8 + g;
            b[ni][0] = *reinterpret_cast<const unsigned*>(wb + oc * XS_STRIDE + k0 + tig * 2);
            b[ni][1] = *reinterpret_cast<const unsigned*>(wb + oc * XS_STRIDE + k0 + tig * 2 + 8);
        }
#pragma unroll
        for (int mi = 0; mi < 2; mi++)
#pragma unroll
            for (int ni = 0; ni < 2; ni++)
                mma16816(d[mi][ni], a[mi], b[ni]);
    }
}

__global__ __launch_bounds__(256, 2) void gemm_kernel(const float* __restrict__ x,
                                                      const float* __restrict__ W,
                                                      const float* __restrict__ a_l,
                                                      const float* __restrict__ a_r) {
    extern __shared__ __align__(16) char dynsmem[];
    __nv_bfloat16* xs_hi = reinterpret_cast<__nv_bfloat16*>(dynsmem);
    __nv_bfloat16* xs_lo = xs_hi + XS_ELEMS;
    __nv_bfloat16* ws_hi = xs_lo + XS_ELEMS;
    __nv_bfloat16* ws_lo = ws_hi + WS_ELEMS;
    __shared__ float s_el[GEMM_ROWS];
    __shared__ float s_er[GEMM_ROWS];

    int tid = threadIdx.x;
    int row0 = blockIdx.x * GEMM_ROWS;

    if (tid < GEMM_ROWS) { s_el[tid] = 0.0f; s_er[tid] = 0.0f; }

    // stage x (64 rows x 128 cols, split hi/lo)
    for (int i = tid; i < GEMM_ROWS * (IN_CH / 4); i += 256) {
        int r  = i >> 5;
        int c4 = (i & 31) << 2;
        int row = row0 + r;
        float4 v = make_float4(0.f, 0.f, 0.f, 0.f);
        if (row < N_NODES) v = *reinterpret_cast<const float4*>(x + (size_t)row * IN_CH + c4);
        store_split4(xs_hi, xs_lo, r * XS_STRIDE + c4, v);
    }
    // stage W (64 x 128)
    for (int i = tid; i < OUT_CH * (IN_CH / 4); i += 256) {
        int r  = i >> 5;
        int c4 = (i & 31) << 2;
        float4 v = *reinterpret_cast<const float4*>(W + (size_t)r * IN_CH + c4);
        store_split4(ws_hi, ws_lo, r * XS_STRIDE + c4, v);
    }
    __syncthreads();

    int lane = tid & 31, wid = tid >> 5;
    int wm = wid & 1, wn = wid >> 1;      // 2 row-halves x 4 col-quarters
    int g = lane >> 2, tig = lane & 3;

    float d[2][2][4];
#pragma unroll
    for (int mi = 0; mi < 2; mi++)
#pragma unroll
        for (int ni = 0; ni < 2; ni++)
#pragma unroll
            for (int q = 0; q < 4; q++) d[mi][ni][q] = 0.0f;

    gemm_pass(xs_hi, ws_hi, wm, wn, g, tig, d);
    gemm_pass(xs_lo, ws_hi, wm, wn, g, tig, d);
    gemm_pass(xs_hi, ws_lo, wm, wn, g, tig, d);

    float alv[2][2], arv[2][2];
#pragma unroll
    for (int ni = 0; ni < 2; ni++) {
        int c = wn * 16 + ni * 8 + tig * 2;
        alv[ni][0] = a_l[c];     alv[ni][1] = a_l[c + 1];
        arv[ni][0] = a_r[c];     arv[ni][1] = a_r[c + 1];
    }

#pragma unroll
    for (int mi = 0; mi < 2; mi++) {
        int r1 = wm * 32 + mi * 16 + g;
        int r2 = r1 + 8;
        int grow1 = row0 + r1, grow2 = row0 + r2;
        float sl1 = 0.f, sr1 = 0.f, sl2 = 0.f, sr2 = 0.f;
#pragma unroll
        for (int ni = 0; ni < 2; ni++) {
            int c = wn * 16 + ni * 8 + tig * 2;
            float d0 = d[mi][ni][0], d1 = d[mi][ni][1];
            float d2 = d[mi][ni][2], d3 = d[mi][ni][3];
            sl1 = fmaf(d0, alv[ni][0], fmaf(d1, alv[ni][1], sl1));
            sr1 = fmaf(d0, arv[ni][0], fmaf(d1, arv[ni][1], sr1));
            sl2 = fmaf(d2, alv[ni][0], fmaf(d3, alv[ni][1], sl2));
            sr2 = fmaf(d2, arv[ni][0], fmaf(d3, arv[ni][1], sr2));
            if (grow1 < N_NODES)
                *reinterpret_cast<float2*>(g_h + (size_t)grow1 * OUT_CH + c) = make_float2(d0, d1);
            if (grow2 < N_NODES)
                *reinterpret_cast<float2*>(g_h + (size_t)grow2 * OUT_CH + c) = make_float2(d2, d3);
        }
#pragma unroll
        for (int m = 1; m < 4; m <<= 1) {
            sl1 += __shfl_xor_sync(0xFFFFFFFFu, sl1, m);
            sr1 += __shfl_xor_sync(0xFFFFFFFFu, sr1, m);
            sl2 += __shfl_xor_sync(0xFFFFFFFFu, sl2, m);
            sr2 += __shfl_xor_sync(0xFFFFFFFFu, sr2, m);
        }
        if (tig == 0) {
            atomicAdd(&s_el[r1], sl1); atomicAdd(&s_er[r1], sr1);
            atomicAdd(&s_el[r2], sl2); atomicAdd(&s_er[r2], sr2);
        }
    }
    __syncthreads();
    if (tid < GEMM_ROWS) {
        int row = row0 + tid;
        if (row < N_NODES) { g_el[row] = s_el[tid]; g_er[row] = s_er[tid]; }
    }
}

// ---------------- hist: histogram of dst (4 edges/thread, int4) ----------------
__global__ void hist_kernel(const int* __restrict__ ei) {
    int t = blockIdx.x * blockDim.x + threadIdx.x;
    int e4 = t * 4;
    if (e4 >= N_EDGES) return;
    int4 d = *reinterpret_cast<const int4*>(ei + N_EDGES + e4);
    atomicAdd(&g_deg[d.x], 1);
    atomicAdd(&g_deg[d.y], 1);
    atomicAdd(&g_deg[d.z], 1);
    atomicAdd(&g_deg[d.w], 1);
}

// ---------------- scan a: per-block inclusive scan of deg ----------------
__global__ void scan_block_kernel() {
    __shared__ int warp_sums[32];
    int i = blockIdx.x * SCAN_BS + threadIdx.x;
    int lane = threadIdx.x & 31, wid = threadIdx.x >> 5;
    int v = (i < N_NODES) ? g_deg[i] : 0;
    int s = v;
#pragma unroll
    for (int o = 1; o < 32; o <<= 1) {
        int t = __shfl_up_sync(0xFFFFFFFFu, s, o);
        if (lane >= o) s += t;
    }
    if (lane == 31) warp_sums[wid] = s;
    __syncthreads();
    if (wid == 0) {
        int ws = warp_sums[lane];
#pragma unroll
        for (int o = 1; o < 32; o <<= 1) {
            int t = __shfl_up_sync(0xFFFFFFFFu, ws, o);
            if (lane >= o) ws += t;
        }
        warp_sums[lane] = ws;
    }
    __syncthreads();
    int incl = s + (wid > 0 ? warp_sums[wid - 1] : 0);
    if (i < N_NODES) g_rowptr[i + 1] = incl;
    if (threadIdx.x == SCAN_BS - 1) g_bsum[blockIdx.x] = incl;
}

// ---------------- scan b: exclusive scan of block sums (1 block) ----------------
__global__ void scan_bsum_kernel() {
    __shared__ int sh[NUM_SCAN_BLOCKS];
    int t = threadIdx.x;
    if (t < NUM_SCAN_BLOCKS) sh[t] = g_bsum[t];
    __syncthreads();
    if (t == 0) {
        int run = 0;
        for (int b = 0; b < NUM_SCAN_BLOCKS; b++) {
            int v = sh[b];
            sh[b] = run;
            run += v;
        }
    }
    __syncthreads();
    if (t < NUM_SCAN_BLOCKS) g_bsum[t] = sh[t];
}

// ---------------- scan c: finalize rowptr AND preload g_fill ----------------
__global__ void scan_add_kernel() {
    int i = blockIdx.x * blockDim.x + threadIdx.x;
    if (i < N_NODES) {
        int v = g_rowptr[i + 1] + g_bsum[i >> 10];
        g_rowptr[i + 1] = v;
        if (i + 1 < N_NODES) g_fill[i + 1] = v;
    }
    if (i == 0) { g_rowptr[0] = 0; g_fill[0] = 0; }
}

// ---------------- scatter: store (src, er) CSR-ordered (R9 form) ----------------
__global__ void scatter_kernel(const int* __restrict__ ei) {
    int t = blockIdx.x * blockDim.x + threadIdx.x;
    int e4 = t * 4;
    if (e4 >= N_EDGES) return;
    int4 s = *reinterpret_cast<const int4*>(ei + e4);
    int4 d = *reinterpret_cast<const int4*>(ei + N_EDGES + e4);
#pragma unroll
    for (int j = 0; j < 4; j++) {
        int src = (j == 0) ? s.x : (j == 1) ? s.y : (j == 2) ? s.z : s.w;
        int dst = (j == 0) ? d.x : (j == 1) ? d.y : (j == 2) ? d.z : d.w;
        int pos = atomicAdd(&g_fill[dst], 1);
        g_edge_sorted[pos] = make_int2(src, __float_as_int(g_er[src]));
    }
}

// ---------------- msg: softmax + gather, 2 warps per node, unroll x4 (R9 form) ----------------
// NOTE: max-shift dropped; differs from reference by eps*(e^max-1)/sum ~ 3e-8.
__global__ void msg_kernel(float* __restrict__ out, const float* __restrict__ bias) {
    int gtid = blockIdx.x * blockDim.x + threadIdx.x;
    int w = gtid >> 5;
    int node = w >> 1;
    if (node >= N_NODES) return;
    int half = w & 1;
    int lane = gtid & 31;
    int chan = half * 32 + lane;
    int p   = g_rowptr[node];
    int end = g_rowptr[node + 1];
    float el = g_el[node];
    float acc = 0.0f, wsum = 0.0f;
    for (; p + 4 <= end; p += 4) {
        int2 e0 = g_edge_sorted[p];
        int2 e1 = g_edge_sorted[p + 1];
        int2 e2 = g_edge_sorted[p + 2];
        int2 e3 = g_edge_sorted[p + 3];
        float h0 = g_h[(size_t)e0.x * OUT_CH + chan];
        float h1 = g_h[(size_t)e1.x * OUT_CH + chan];
        float h2 = g_h[(size_t)e2.x * OUT_CH + chan];
        float h3 = g_h[(size_t)e3.x * OUT_CH + chan];
        float w0 = __expf(leaky(el + __int_as_float(e0.y)));
        float w1 = __expf(leaky(el + __int_as_float(e1.y)));
        float w2 = __expf(leaky(el + __int_as_float(e2.y)));
        float w3 = __expf(leaky(el + __int_as_float(e3.y)));
        wsum += (w0 + w1) + (w2 + w3);
        acc = fmaf(w0, h0, acc);
        acc = fmaf(w1, h1, acc);
        acc = fmaf(w2, h2, acc);
        acc = fmaf(w3, h3, acc);
    }
    for (; p < end; p++) {
        int2 e0 = g_edge_sorted[p];
        float w0 = __expf(leaky(el + __int_as_float(e0.y)));
        wsum += w0;
        acc = fmaf(w0, g_h[(size_t)e0.x * OUT_CH + chan], acc);
    }
    out[(size_t)node * OUT_CH + chan] = acc / (wsum + EPS_F) + bias[chan];
}

// ---------------- launch ----------------
extern "C" void kernel_launch(void* const* d_in, const int* in_sizes, int n_in,
                              void* d_out, int out_size) {
    const float* x    = (const float*)d_in[0];
    const int*   ei   = (const int*)d_in[1];     // int32 (JAX x64 disabled)
    const float* W    = (const float*)d_in[2];
    const float* a_l  = (const float*)d_in[3];
    const float* a_r  = (const float*)d_in[4];
    const float* bias = (const float*)d_in[5];
    float* out = (float*)d_out;

    (void)in_sizes; (void)n_in; (void)out_size;

    cudaFuncSetAttribute(gemm_kernel, cudaFuncAttributeMaxDynamicSharedMemorySize,
                         GEMM_SMEM_BYTES);

    // gemm kept at launch index 3 (ncu profiles index 3).
    init_kernel<<<(N_NODES + 255) / 256, 256>>>();                    // 0
    hist_kernel<<<(N_EDGES / 4 + 255) / 256, 256>>>(ei);              // 1
    scan_block_kernel<<<NUM_SCAN_BLOCKS, SCAN_BS>>>();                // 2
    gemm_kernel<<<(N_NODES + GEMM_ROWS - 1) / GEMM_ROWS, 256,
                  GEMM_SMEM_BYTES>>>(x, W, a_l, a_r);                 // 3  <-- profiled
    scan_bsum_kernel<<<1, 128>>>();                                   // 4
    scan_add_kernel<<<(N_NODES + 255) / 256, 256>>>();                // 5
    scatter_kernel<<<(N_EDGES / 4 + 255) / 256, 256>>>(ei);           // 6
    {
        long long threads = (long long)N_NODES * 64;   // 2 warps per node
        int blocks = (int)((threads + 255) / 256);
        msg_kernel<<<blocks, 256>>>(out, bias);                       // 7
    }
}

// round 14
// speedup vs baseline: 1.9368x; 1.1971x over previous
#include <cuda_runtime.h>
#include <cuda_bf16.h>
#include <cuda_fp16.h>
#include <math_constants.h>

#define N_NODES 100000
#define N_EDGES 1600000
#define IN_CH   128
#define OUT_CH  64
#define NEG_SLOPE 0.2f
#define EPS_F 1e-10f

#define SCAN_BS 1024
#define NUM_SCAN_BLOCKS ((N_NODES + SCAN_BS - 1) / SCAN_BS)   // 98

// ---------------- scratch (no allocations allowed) ----------------
__device__ __half g_h[(size_t)N_NODES * OUT_CH];  // 12.8 MB (fp16)
__device__ float g_el[N_NODES];
__device__ float g_er[N_NODES];
__device__ int   g_deg[N_NODES];
__device__ int   g_fill[N_NODES];                 // preloaded with rowptr starts
__device__ int   g_rowptr[N_NODES + 1];
__device__ int   g_bsum[NUM_SCAN_BLOCKS];
__device__ int2  g_edge_sorted[N_EDGES];          // (src, er-bits) 12.8 MB

__device__ __forceinline__ float leaky(float v) {
    return v > 0.0f ? v : NEG_SLOPE * v;
}

// ---------------- K0: zero deg ----------------
__global__ void init_kernel() {
    int i = blockIdx.x * blockDim.x + threadIdx.x;
    if (i < N_NODES) g_deg[i] = 0;
}

// ================= gemm: split-bf16 tensor-core GEMM + fused elr =================
#define GEMM_ROWS 64
#define XS_STRIDE 136
#define XS_ELEMS  (GEMM_ROWS * XS_STRIDE)
#define WS_ELEMS  (OUT_CH * XS_STRIDE)
#define GEMM_SMEM_BYTES ((2 * XS_ELEMS + 2 * WS_ELEMS) * 2)   // 69632

__device__ __forceinline__ void store_split4(__nv_bfloat16* hi, __nv_bfloat16* lo,
                                             int idx, float4 v) {
    float f[4] = {v.x, v.y, v.z, v.w};
    unsigned hb[4], lb[4];
#pragma unroll
    for (int j = 0; j < 4; j++) {
        __nv_bfloat16 h = __float2bfloat16_rn(f[j]);
        float hf = __bfloat162float(h);
        __nv_bfloat16 l = __float2bfloat16_rn(f[j] - hf);
        hb[j] = (unsigned)__bfloat16_as_ushort(h);
        lb[j] = (unsigned)__bfloat16_as_ushort(l);
    }
    unsigned* ph = reinterpret_cast<unsigned*>(hi + idx);
    unsigned* pl = reinterpret_cast<unsigned*>(lo + idx);
    ph[0] = hb[0] | (hb[1] << 16);
    ph[1] = hb[2] | (hb[3] << 16);
    pl[0] = lb[0] | (lb[1] << 16);
    pl[1] = lb[2] | (lb[3] << 16);
}

__device__ __forceinline__ void mma16816(float d[4], const unsigned a[4], const unsigned b[2]) {
    asm volatile(
        "mma.sync.aligned.m16n8k16.row.col.f32.bf16.bf16.f32 "
        "{%0,%1,%2,%3}, {%4,%5,%6,%7}, {%8,%9}, {%0,%1,%2,%3};\n"
        : "+f"(d[0]), "+f"(d[1]), "+f"(d[2]), "+f"(d[3])
        : "r"(a[0]), "r"(a[1]), "r"(a[2]), "r"(a[3]), "r"(b[0]), "r"(b[1]));
}

__device__ __forceinline__ void gemm_pass(const __nv_bfloat16* xa, const __nv_bfloat16* wb,
                                          int wm, int wn, int g, int tig,
                                          float d[2][2][4]) {
#pragma unroll
    for (int ks = 0; ks < 8; ks++) {
        int k0 = ks * 16;
        unsigned a[2][4];
        unsigned b[2][2];
#pragma unroll
        for (int mi = 0; mi < 2; mi++) {
            int rb = wm * 32 + mi * 16;
            a[mi][0] = *reinterpret_cast<const unsigned*>(xa + (rb + g)     * XS_STRIDE + k0 + tig * 2);
            a[mi][1] = *reinterpret_cast<const unsigned*>(xa + (rb + g + 8) * XS_STRIDE + k0 + tig * 2);
            a[mi][2] = *reinterpret_cast<const unsigned*>(xa + (rb + g)     * XS_STRIDE + k0 + tig * 2 + 8);
            a[mi][3] = *reinterpret_cast<const unsigned*>(xa + (rb + g + 8) * XS_STRIDE + k0 + tig * 2 + 8);
        }
#pragma unroll
        for (int ni = 0; ni < 2; ni++) {
            int oc = wn * 16 + ni * 8 + g;
            b[ni][0] = *reinterpret_cast<const unsigned*>(wb + oc * XS_STRIDE + k0 + tig * 2);
            b[ni][1] = *reinterpret_cast<const unsigned*>(wb + oc * XS_STRIDE + k0 + tig * 2 + 8);
        }
#pragma unroll
        for (int mi = 0; mi < 2; mi++)
#pragma unroll
            for (int ni = 0; ni < 2; ni++)
                mma16816(d[mi][ni], a[mi], b[ni]);
    }
}

__global__ __launch_bounds__(256, 2) void gemm_kernel(const float* __restrict__ x,
                                                      const float* __restrict__ W,
                                                      const float* __restrict__ a_l,
                                                      const float* __restrict__ a_r) {
    extern __shared__ __align__(16) char dynsmem[];
    __nv_bfloat16* xs_hi = reinterpret_cast<__nv_bfloat16*>(dynsmem);
    __nv_bfloat16* xs_lo = xs_hi + XS_ELEMS;
    __nv_bfloat16* ws_hi = xs_lo + XS_ELEMS;
    __nv_bfloat16* ws_lo = ws_hi + WS_ELEMS;
    __shared__ float s_el[GEMM_ROWS];
    __shared__ float s_er[GEMM_ROWS];

    int tid = threadIdx.x;
    int row0 = blockIdx.x * GEMM_ROWS;

    if (tid < GEMM_ROWS) { s_el[tid] = 0.0f; s_er[tid] = 0.0f; }

    for (int i = tid; i < GEMM_ROWS * (IN_CH / 4); i += 256) {
        int r  = i >> 5;
        int c4 = (i & 31) << 2;
        int row = row0 + r;
        float4 v = make_float4(0.f, 0.f, 0.f, 0.f);
        if (row < N_NODES) v = *reinterpret_cast<const float4*>(x + (size_t)row * IN_CH + c4);
        store_split4(xs_hi, xs_lo, r * XS_STRIDE + c4, v);
    }
    for (int i = tid; i < OUT_CH * (IN_CH / 4); i += 256) {
        int r  = i >> 5;
        int c4 = (i & 31) << 2;
        float4 v = *reinterpret_cast<const float4*>(W + (size_t)r * IN_CH + c4);
        store_split4(ws_hi, ws_lo, r * XS_STRIDE + c4, v);
    }
    __syncthreads();

    int lane = tid & 31, wid = tid >> 5;
    int wm = wid & 1, wn = wid >> 1;
    int g = lane >> 2, tig = lane & 3;

    float d[2][2][4];
#pragma unroll
    for (int mi = 0; mi < 2; mi++)
#pragma unroll
        for (int ni = 0; ni < 2; ni++)
#pragma unroll
            for (int q = 0; q < 4; q++) d[mi][ni][q] = 0.0f;

    gemm_pass(xs_hi, ws_hi, wm, wn, g, tig, d);
    gemm_pass(xs_lo, ws_hi, wm, wn, g, tig, d);
    gemm_pass(xs_hi, ws_lo, wm, wn, g, tig, d);

    float alv[2][2], arv[2][2];
#pragma unroll
    for (int ni = 0; ni < 2; ni++) {
        int c = wn * 16 + ni * 8 + tig * 2;
        alv[ni][0] = a_l[c];     alv[ni][1] = a_l[c + 1];
        arv[ni][0] = a_r[c];     arv[ni][1] = a_r[c + 1];
    }

#pragma unroll
    for (int mi = 0; mi < 2; mi++) {
        int r1 = wm * 32 + mi * 16 + g;
        int r2 = r1 + 8;
        int grow1 = row0 + r1, grow2 = row0 + r2;
        float sl1 = 0.f, sr1 = 0.f, sl2 = 0.f, sr2 = 0.f;
#pragma unroll
        for (int ni = 0; ni < 2; ni++) {
            int c = wn * 16 + ni * 8 + tig * 2;
            float d0 = d[mi][ni][0], d1 = d[mi][ni][1];
            float d2 = d[mi][ni][2], d3 = d[mi][ni][3];
            sl1 = fmaf(d0, alv[ni][0], fmaf(d1, alv[ni][1], sl1));
            sr1 = fmaf(d0, arv[ni][0], fmaf(d1, arv[ni][1], sr1));
            sl2 = fmaf(d2, alv[ni][0], fmaf(d3, alv[ni][1], sl2));
            sr2 = fmaf(d2, arv[ni][0], fmaf(d3, arv[ni][1], sr2));
            if (grow1 < N_NODES)
                *reinterpret_cast<__half2*>(g_h + (size_t)grow1 * OUT_CH + c) =
                    __floats2half2_rn(d0, d1);
            if (grow2 < N_NODES)
                *reinterpret_cast<__half2*>(g_h + (size_t)grow2 * OUT_CH + c) =
                    __floats2half2_rn(d2, d3);
        }
#pragma unroll
        for (int m = 1; m < 4; m <<= 1) {
            sl1 += __shfl_xor_sync(0xFFFFFFFFu, sl1, m);
            sr1 += __shfl_xor_sync(0xFFFFFFFFu, sr1, m);
            sl2 += __shfl_xor_sync(0xFFFFFFFFu, sl2, m);
            sr2 += __shfl_xor_sync(0xFFFFFFFFu, sr2, m);
        }
        if (tig == 0) {
            atomicAdd(&s_el[r1], sl1); atomicAdd(&s_er[r1], sr1);
            atomicAdd(&s_el[r2], sl2); atomicAdd(&s_er[r2], sr2);
        }
    }
    __syncthreads();
    if (tid < GEMM_ROWS) {
        int row = row0 + tid;
        if (row < N_NODES) { g_el[row] = s_el[tid]; g_er[row] = s_er[tid]; }
    }
}

// ---------------- hist ----------------
__global__ void hist_kernel(const int* __restrict__ ei) {
    int t = blockIdx.x * blockDim.x + threadIdx.x;
    int e4 = t * 4;
    if (e4 >= N_EDGES) return;
    int4 d = *reinterpret_cast<const int4*>(ei + N_EDGES + e4);
    atomicAdd(&g_deg[d.x], 1);
    atomicAdd(&g_deg[d.y], 1);
    atomicAdd(&g_deg[d.z], 1);
    atomicAdd(&g_deg[d.w], 1);
}

// ---------------- scan a ----------------
__global__ void scan_block_kernel() {
    __shared__ int warp_sums[32];
    int i = blockIdx.x * SCAN_BS + threadIdx.x;
    int lane = threadIdx.x & 31, wid = threadIdx.x >> 5;
    int v = (i < N_NODES) ? g_deg[i] : 0;
    int s = v;
#pragma unroll
    for (int o = 1; o < 32; o <<= 1) {
        int t = __shfl_up_sync(0xFFFFFFFFu, s, o);
        if (lane >= o) s += t;
    }
    if (lane == 31) warp_sums[wid] = s;
    __syncthreads();
    if (wid == 0) {
        int ws = warp_sums[lane];
#pragma unroll
        for (int o = 1; o < 32; o <<= 1) {
            int t = __shfl_up_sync(0xFFFFFFFFu, ws, o);
            if (lane >= o) ws += t;
        }
        warp_sums[lane] = ws;
    }
    __syncthreads();
    int incl = s + (wid > 0 ? warp_sums[wid - 1] : 0);
    if (i < N_NODES) g_rowptr[i + 1] = incl;
    if (threadIdx.x == SCAN_BS - 1) g_bsum[blockIdx.x] = incl;
}

// ---------------- scan b ----------------
__global__ void scan_bsum_kernel() {
    __shared__ int sh[NUM_SCAN_BLOCKS];
    int t = threadIdx.x;
    if (t < NUM_SCAN_BLOCKS) sh[t] = g_bsum[t];
    __syncthreads();
    if (t == 0) {
        int run = 0;
        for (int b = 0; b < NUM_SCAN_BLOCKS; b++) {
            int v = sh[b];
            sh[b] = run;
            run += v;
        }
    }
    __syncthreads();
    if (t < NUM_SCAN_BLOCKS) g_bsum[t] = sh[t];
}

// ---------------- scan c ----------------
__global__ void scan_add_kernel() {
    int i = blockIdx.x * blockDim.x + threadIdx.x;
    if (i < N_NODES) {
        int v = g_rowptr[i + 1] + g_bsum[i >> 10];
        g_rowptr[i + 1] = v;
        if (i + 1 < N_NODES) g_fill[i + 1] = v;
    }
    if (i == 0) { g_rowptr[0] = 0; g_fill[0] = 0; }
}

// ---------------- scatter: store (src, er) CSR-ordered ----------------
__global__ void scatter_kernel(const int* __restrict__ ei) {
    int t = blockIdx.x * blockDim.x + threadIdx.x;
    int e4 = t * 4;
    if (e4 >= N_EDGES) return;
    int4 s = *reinterpret_cast<const int4*>(ei + e4);
    int4 d = *reinterpret_cast<const int4*>(ei + N_EDGES + e4);
#pragma unroll
    for (int j = 0; j < 4; j++) {
        int src = (j == 0) ? s.x : (j == 1) ? s.y : (j == 2) ? s.z : s.w;
        int dst = (j == 0) ? d.x : (j == 1) ? d.y : (j == 2) ? d.z : d.w;
        int pos = atomicAdd(&g_fill[dst], 1);
        g_edge_sorted[pos] = make_int2(src, __float_as_int(g_er[src]));
    }
}

// ---------------- msg: 1 warp/node, half2 per lane, unroll x4 ----------------
// NOTE: max-shift dropped; differs from reference by eps*(e^max-1)/sum ~ 3e-8.
__global__ void msg_kernel(float* __restrict__ out, const float* __restrict__ bias) {
    int gtid = blockIdx.x * blockDim.x + threadIdx.x;
    int node = gtid >> 5;
    int lane = gtid & 31;
    if (node >= N_NODES) return;
    int p   = g_rowptr[node];
    int end = g_rowptr[node + 1];
    float el = g_el[node];
    float accx = 0.0f, accy = 0.0f, wsum = 0.0f;
    const __half2* hbase = reinterpret_cast<const __half2*>(g_h);
    for (; p + 4 <= end; p += 4) {
        int2 e0 = g_edge_sorted[p];
        int2 e1 = g_edge_sorted[p + 1];
        int2 e2 = g_edge_sorted[p + 2];
        int2 e3 = g_edge_sorted[p + 3];
        __half2 v0 = hbase[(size_t)e0.x * (OUT_CH / 2) + lane];
        __half2 v1 = hbase[(size_t)e1.x * (OUT_CH / 2) + lane];
        __half2 v2 = hbase[(size_t)e2.x * (OUT_CH / 2) + lane];
        __half2 v3 = hbase[(size_t)e3.x * (OUT_CH / 2) + lane];
        float w0 = __expf(leaky(el + __int_as_float(e0.y)));
        float w1 = __expf(leaky(el + __int_as_float(e1.y)));
        float w2 = __expf(leaky(el + __int_as_float(e2.y)));
        float w3 = __expf(leaky(el + __int_as_float(e3.y)));
        wsum += (w0 + w1) + (w2 + w3);
        float2 f0 = __half22float2(v0);
        float2 f1 = __half22float2(v1);
        float2 f2 = __half22float2(v2);
        float2 f3 = __half22float2(v3);
        accx = fmaf(w0, f0.x, accx); accy = fmaf(w0, f0.y, accy);
        accx = fmaf(w1, f1.x, accx); accy = fmaf(w1, f1.y, accy);
        accx = fmaf(w2, f2.x, accx); accy = fmaf(w2, f2.y, accy);
        accx = fmaf(w3, f3.x, accx); accy = fmaf(w3, f3.y, accy);
    }
    for (; p < end; p++) {
        int2 e0 = g_edge_sorted[p];
        float w0 = __expf(leaky(el + __int_as_float(e0.y)));
        wsum += w0;
        float2 f0 = __half22float2(hbase[(size_t)e0.x * (OUT_CH / 2) + lane]);
        accx = fmaf(w0, f0.x, accx);
        accy = fmaf(w0, f0.y, accy);
    }
    float inv = 1.0f / (wsum + EPS_F);
    int c = lane * 2;
    *reinterpret_cast<float2*>(out + (size_t)node * OUT_CH + c) =
        make_float2(accx * inv + bias[c], accy * inv + bias[c + 1]);
}

// ---------------- launch ----------------
extern "C" void kernel_launch(void* const* d_in, const int* in_sizes, int n_in,
                              void* d_out, int out_size) {
    const float* x    = (const float*)d_in[0];
    const int*   ei   = (const int*)d_in[1];     // int32 (JAX x64 disabled)
    const float* W    = (const float*)d_in[2];
    const float* a_l  = (const float*)d_in[3];
    const float* a_r  = (const float*)d_in[4];
    const float* bias = (const float*)d_in[5];
    float* out = (float*)d_out;

    (void)in_sizes; (void)n_in; (void)out_size;

    cudaFuncSetAttribute(gemm_kernel, cudaFuncAttributeMaxDynamicSharedMemorySize,
                         GEMM_SMEM_BYTES);

    init_kernel<<<(N_NODES + 255) / 256, 256>>>();                    // 0
    hist_kernel<<<(N_EDGES / 4 + 255) / 256, 256>>>(ei);              // 1
    scan_block_kernel<<<NUM_SCAN_BLOCKS, SCAN_BS>>>();                // 2
    gemm_kernel<<<(N_NODES + GEMM_ROWS - 1) / GEMM_ROWS, 256,
                  GEMM_SMEM_BYTES>>>(x, W, a_l, a_r);                 // 3  <-- profiled
    scan_bsum_kernel<<<1, 128>>>();                                   // 4
    scan_add_kernel<<<(N_NODES + 255) / 256, 256>>>();                // 5
    scatter_kernel<<<(N_EDGES / 4 + 255) / 256, 256>>>(ei);           // 6
    {
        long long threads = (long long)N_NODES * 32;   // 1 warp per node
        int blocks = (int)((threads + 255) / 256);
        msg_kernel<<<blocks, 256>>>(out, bias);                       // 7
    }
}